// round 16
// baseline (speedup 1.0000x reference)
#include <cuda_runtime.h>

// C[b,g] = softor_s( softand_l( x[b, I[g,s,l]] ) ),  gamma = 1e-3
// B=64, G=2048, S=32, L=8
//
// Scaled domain: w = -x * KINV  (KINV = 1/(gamma*ln2))
//   softand':  mW = max_l w,  sum = sum_l exp2(w_l - mW),  aw = mW + lg2(sum)
//   softor' :  Mw = min_s aw,  S = sum_s exp2(Mw - aw_s)
//              C  = (lg2(S) - Mw) * gamma*ln2
//
// R6 proven-best scalar body. New this round: PreferredSharedMemoryCarveout
// = max L1, growing L1D toward 224KB so the 512KB gather table hits L1 more
// often (gather-latency exposure is the measured binder).

#define NB 64
#define NG 2048
#define NS 32
#define NL 8
#define NCHUNK 8              // s-dimension split across 8 warps
#define SPER (NS / NCHUNK)    // 4 s-values per chunk
#define NTHR (NCHUNK * 32)    // 256 threads

#define KINV 1442.6950408889634f
#define GLN2 0.0006931471805599453f

// Transposed, negated, scaled x: w[g][b] = -x[b][g] * KINV.
__device__ float g_w[NG * NB];

// Tiled transpose 64x2048 -> 2048x64, coalesced both sides; fuses -x*KINV.
__global__ void transpose_kernel(const float* __restrict__ x) {
    __shared__ float tile[32][33];
    const int gx = blockIdx.x * 32;
    const int bx = blockIdx.y * 32;
    const int tx = threadIdx.x;
    const int ty = threadIdx.y;
#pragma unroll
    for (int i = 0; i < 32; i += 8)
        tile[ty + i][tx] = x[(bx + ty + i) * NG + gx + tx] * (-KINV);
    __syncthreads();
#pragma unroll
    for (int i = 0; i < 32; i += 8)
        g_w[(gx + ty + i) * NB + bx + tx] = tile[tx][ty + i];
#if __CUDA_ARCH__ >= 900
    // Trigger AFTER the g_w stores (these must be visible to the dependent
    // grid at its cudaGridDependencySynchronize).
    cudaTriggerProgrammaticLaunchCompletion();
#endif
}

__device__ __forceinline__ float ex2_approx(float t) {
    float r;
    asm("ex2.approx.ftz.f32 %0, %1;" : "=f"(r) : "f"(t));
    return r;
}
__device__ __forceinline__ float lg2_approx(float t) {
    float r;
    asm("lg2.approx.f32 %0, %1;" : "=f"(r) : "f"(t));
    return r;
}

// One block (256 threads) per g:
//   warp w handles s in [w*4, w*4+4); lane covers b = 2*lane, 2*lane+1.
__global__ __launch_bounds__(NTHR) void clause_kernel(
    const int* __restrict__ I,  // [NG, NS, NL] int32
    float* __restrict__ out)    // [NB, NG]
{
    const int g = blockIdx.x;
    const int tid = threadIdx.x;
    const int lane = tid & 31;
    const int chunk = tid >> 5;

    __shared__ int soff[NS * NL];          // pre-shifted byte offsets
    __shared__ float2 pM2[NCHUNK][NB / 2]; // partial min(aw) per chunk
    __shared__ float2 pS2[NCHUNK][NB / 2]; // partial sum-of-exp per chunk

    // Prologue: independent of g_w — overlaps with the transpose under PDL.
    if (tid < NS * NL / 4) {
        int4 r = ((const int4*)(I + g * (NS * NL)))[tid];
        r.x = (r.x & (NG - 1)) << 8;   // *256 bytes = row stride in bytes
        r.y = (r.y & (NG - 1)) << 8;
        r.z = (r.z & (NG - 1)) << 8;
        r.w = (r.w & (NG - 1)) << 8;
        ((int4*)soff)[tid] = r;
    }
    __syncthreads();

#if __CUDA_ARCH__ >= 900
    cudaGridDependencySynchronize();
#endif

    const char* lanebase = (const char*)g_w + lane * sizeof(float2);
    const int4* __restrict__ soff4 = (const int4*)soff;

    float awx[SPER], awy[SPER];

#pragma unroll
    for (int si = 0; si < SPER; si++) {
        const int s = chunk * SPER + si;
        const int4 o0 = soff4[s * 2 + 0];
        const int4 o1 = soff4[s * 2 + 1];

        float2 w0 = *(const float2*)(lanebase + o0.x);
        float2 w1 = *(const float2*)(lanebase + o0.y);
        float2 w2 = *(const float2*)(lanebase + o0.z);
        float2 w3 = *(const float2*)(lanebase + o0.w);
        float2 w4 = *(const float2*)(lanebase + o1.x);
        float2 w5 = *(const float2*)(lanebase + o1.y);
        float2 w6 = *(const float2*)(lanebase + o1.z);
        float2 w7 = *(const float2*)(lanebase + o1.w);

        float mx = fmaxf(fmaxf(fmaxf(w0.x, w1.x), fmaxf(w2.x, w3.x)),
                         fmaxf(fmaxf(w4.x, w5.x), fmaxf(w6.x, w7.x)));
        float my = fmaxf(fmaxf(fmaxf(w0.y, w1.y), fmaxf(w2.y, w3.y)),
                         fmaxf(fmaxf(w4.y, w5.y), fmaxf(w6.y, w7.y)));

        float sx = ex2_approx(w0.x - mx) + ex2_approx(w1.x - mx)
                 + ex2_approx(w2.x - mx) + ex2_approx(w3.x - mx)
                 + ex2_approx(w4.x - mx) + ex2_approx(w5.x - mx)
                 + ex2_approx(w6.x - mx) + ex2_approx(w7.x - mx);
        float sy = ex2_approx(w0.y - my) + ex2_approx(w1.y - my)
                 + ex2_approx(w2.y - my) + ex2_approx(w3.y - my)
                 + ex2_approx(w4.y - my) + ex2_approx(w5.y - my)
                 + ex2_approx(w6.y - my) + ex2_approx(w7.y - my);

        awx[si] = mx + lg2_approx(sx);
        awy[si] = my + lg2_approx(sy);
    }

    // Partial softor over this chunk's SPER aw values (min in w-domain).
    float Mwx = fminf(fminf(awx[0], awx[1]), fminf(awx[2], awx[3]));
    float Mwy = fminf(fminf(awy[0], awy[1]), fminf(awy[2], awy[3]));
    float Sx = ex2_approx(Mwx - awx[0]) + ex2_approx(Mwx - awx[1])
             + ex2_approx(Mwx - awx[2]) + ex2_approx(Mwx - awx[3]);
    float Sy = ex2_approx(Mwy - awy[0]) + ex2_approx(Mwy - awy[1])
             + ex2_approx(Mwy - awy[2]) + ex2_approx(Mwy - awy[3]);

    pM2[chunk][lane] = make_float2(Mwx, Mwy);
    pS2[chunk][lane] = make_float2(Sx, Sy);
    __syncthreads();

    // First 64 threads: merge NCHUNK partials per b and write out.
    if (tid < NB) {
        const int b = tid;
        const float* pM = (const float*)pM2;  // [NCHUNK][NB]
        const float* pS = (const float*)pS2;
        float Mw = pM[b];
#pragma unroll
        for (int c = 1; c < NCHUNK; c++) Mw = fminf(Mw, pM[c * NB + b]);
        float S = 0.0f;
#pragma unroll
        for (int c = 0; c < NCHUNK; c++)
            S = fmaf(pS[c * NB + b], ex2_approx(Mw - pM[c * NB + b]), S);
        out[b * NG + g] = (lg2_approx(S) - Mw) * GLN2;
    }
}

extern "C" void kernel_launch(void* const* d_in, const int* in_sizes, int n_in,
                              void* d_out, int out_size) {
    // Identify inputs by element count:
    //   x:  64*2048   = 131072 float32
    //   I:  2048*32*8 = 524288 int32
    const float* x = nullptr;
    const int* I = nullptr;
    for (int i = 0; i < n_in; i++) {
        if (in_sizes[i] == NB * NG)           x = (const float*)d_in[i];
        else if (in_sizes[i] == NG * NS * NL) I = (const int*)d_in[i];
    }

    float* out = (float*)d_out;  // [64, 2048] fp32

    // Maximize L1D (228KB unified minus carveout): the 512KB gather table's
    // L1 hit rate is the measured bottleneck. Host-side attr, alloc-free.
    cudaFuncSetAttribute(clause_kernel,
                         cudaFuncAttributePreferredSharedMemoryCarveout,
                         cudaSharedmemCarveoutMaxL1);
    cudaFuncSetAttribute(transpose_kernel,
                         cudaFuncAttributePreferredSharedMemoryCarveout,
                         cudaSharedmemCarveoutMaxL1);

    dim3 tgrid(NG / 32, NB / 32);
    dim3 tblock(32, 8);
    transpose_kernel<<<tgrid, tblock>>>(x);

    // PDL: clause_kernel launches early; gates on transpose completion
    // (trigger placed after the g_w stores) before touching g_w.
    cudaLaunchConfig_t cfg = {};
    cfg.gridDim = dim3(NG);
    cfg.blockDim = dim3(NTHR);
    cfg.dynamicSmemBytes = 0;
    cfg.stream = 0;
    cudaLaunchAttribute attr[1];
    attr[0].id = cudaLaunchAttributeProgrammaticStreamSerialization;
    attr[0].val.programmaticStreamSerializationAllowed = 1;
    cfg.attrs = attr;
    cfg.numAttrs = 1;
    cudaLaunchKernelEx(&cfg, clause_kernel, I, (float*)d_out);
}

// round 17
// speedup vs baseline: 2.0701x; 2.0701x over previous
#include <cuda_runtime.h>

// C[b,g] = softor_s( softand_l( x[b, I[g,s,l]] ) ),  gamma = 1e-3
// B=64, G=2048, S=32, L=8
//
// Scaled domain: w = -x * KINV  (KINV = 1/(gamma*ln2))
//   softand':  mW = max_l w,  sum = sum_l exp2(w_l - mW),  aw = mW + lg2(sum)
//   softor' :  Mw = min_s aw,  S = sum_s exp2(Mw - aw_s)
//              C  = (lg2(S) - Mw) * gamma*ln2
//
// Best-measured configuration: R6 scalar body + PDL (after-stores trigger)
// + __ldg (read-only LDG path) on the random gathers.

#define NB 64
#define NG 2048
#define NS 32
#define NL 8
#define NCHUNK 8              // s-dimension split across 8 warps
#define SPER (NS / NCHUNK)    // 4 s-values per chunk
#define NTHR (NCHUNK * 32)    // 256 threads

#define KINV 1442.6950408889634f
#define GLN2 0.0006931471805599453f

// Transposed, negated, scaled x: w[g][b] = -x[b][g] * KINV.
__device__ float g_w[NG * NB];

// Tiled transpose 64x2048 -> 2048x64, coalesced both sides; fuses -x*KINV.
__global__ void transpose_kernel(const float* __restrict__ x) {
    __shared__ float tile[32][33];
    const int gx = blockIdx.x * 32;
    const int bx = blockIdx.y * 32;
    const int tx = threadIdx.x;
    const int ty = threadIdx.y;
#pragma unroll
    for (int i = 0; i < 32; i += 8)
        tile[ty + i][tx] = x[(bx + ty + i) * NG + gx + tx] * (-KINV);
    __syncthreads();
#pragma unroll
    for (int i = 0; i < 32; i += 8)
        g_w[(gx + ty + i) * NB + bx + tx] = tile[tx][ty + i];
#if __CUDA_ARCH__ >= 900
    // Trigger AFTER the g_w stores (these must be visible to the dependent
    // grid at its cudaGridDependencySynchronize).
    cudaTriggerProgrammaticLaunchCompletion();
#endif
}

__device__ __forceinline__ float ex2_approx(float t) {
    float r;
    asm("ex2.approx.ftz.f32 %0, %1;" : "=f"(r) : "f"(t));
    return r;
}
__device__ __forceinline__ float lg2_approx(float t) {
    float r;
    asm("lg2.approx.f32 %0, %1;" : "=f"(r) : "f"(t));
    return r;
}

// Read-only gather: LDG.E.CONSTANT path.
__device__ __forceinline__ float2 ldg2(const char* p) {
    return __ldg((const float2*)p);
}

// One block (256 threads) per g:
//   warp w handles s in [w*4, w*4+4); lane covers b = 2*lane, 2*lane+1.
__global__ __launch_bounds__(NTHR) void clause_kernel(
    const int* __restrict__ I,  // [NG, NS, NL] int32
    float* __restrict__ out)    // [NB, NG]
{
    const int g = blockIdx.x;
    const int tid = threadIdx.x;
    const int lane = tid & 31;
    const int chunk = tid >> 5;

    __shared__ int soff[NS * NL];          // pre-shifted byte offsets
    __shared__ float2 pM2[NCHUNK][NB / 2]; // partial min(aw) per chunk
    __shared__ float2 pS2[NCHUNK][NB / 2]; // partial sum-of-exp per chunk

    // Prologue: independent of g_w — overlaps with the transpose under PDL.
    if (tid < NS * NL / 4) {
        int4 r = ((const int4*)(I + g * (NS * NL)))[tid];
        r.x = (r.x & (NG - 1)) << 8;   // *256 bytes = row stride in bytes
        r.y = (r.y & (NG - 1)) << 8;
        r.z = (r.z & (NG - 1)) << 8;
        r.w = (r.w & (NG - 1)) << 8;
        ((int4*)soff)[tid] = r;
    }
    __syncthreads();

#if __CUDA_ARCH__ >= 900
    cudaGridDependencySynchronize();
#endif

    const char* lanebase = (const char*)g_w + lane * sizeof(float2);
    const int4* __restrict__ soff4 = (const int4*)soff;

    float awx[SPER], awy[SPER];

#pragma unroll
    for (int si = 0; si < SPER; si++) {
        const int s = chunk * SPER + si;
        const int4 o0 = soff4[s * 2 + 0];
        const int4 o1 = soff4[s * 2 + 1];

        float2 w0 = ldg2(lanebase + o0.x);
        float2 w1 = ldg2(lanebase + o0.y);
        float2 w2 = ldg2(lanebase + o0.z);
        float2 w3 = ldg2(lanebase + o0.w);
        float2 w4 = ldg2(lanebase + o1.x);
        float2 w5 = ldg2(lanebase + o1.y);
        float2 w6 = ldg2(lanebase + o1.z);
        float2 w7 = ldg2(lanebase + o1.w);

        float mx = fmaxf(fmaxf(fmaxf(w0.x, w1.x), fmaxf(w2.x, w3.x)),
                         fmaxf(fmaxf(w4.x, w5.x), fmaxf(w6.x, w7.x)));
        float my = fmaxf(fmaxf(fmaxf(w0.y, w1.y), fmaxf(w2.y, w3.y)),
                         fmaxf(fmaxf(w4.y, w5.y), fmaxf(w6.y, w7.y)));

        float sx = ex2_approx(w0.x - mx) + ex2_approx(w1.x - mx)
                 + ex2_approx(w2.x - mx) + ex2_approx(w3.x - mx)
                 + ex2_approx(w4.x - mx) + ex2_approx(w5.x - mx)
                 + ex2_approx(w6.x - mx) + ex2_approx(w7.x - mx);
        float sy = ex2_approx(w0.y - my) + ex2_approx(w1.y - my)
                 + ex2_approx(w2.y - my) + ex2_approx(w3.y - my)
                 + ex2_approx(w4.y - my) + ex2_approx(w5.y - my)
                 + ex2_approx(w6.y - my) + ex2_approx(w7.y - my);

        awx[si] = mx + lg2_approx(sx);
        awy[si] = my + lg2_approx(sy);
    }

    // Partial softor over this chunk's SPER aw values (min in w-domain).
    float Mwx = fminf(fminf(awx[0], awx[1]), fminf(awx[2], awx[3]));
    float Mwy = fminf(fminf(awy[0], awy[1]), fminf(awy[2], awy[3]));
    float Sx = ex2_approx(Mwx - awx[0]) + ex2_approx(Mwx - awx[1])
             + ex2_approx(Mwx - awx[2]) + ex2_approx(Mwx - awx[3]);
    float Sy = ex2_approx(Mwy - awy[0]) + ex2_approx(Mwy - awy[1])
             + ex2_approx(Mwy - awy[2]) + ex2_approx(Mwy - awy[3]);

    pM2[chunk][lane] = make_float2(Mwx, Mwy);
    pS2[chunk][lane] = make_float2(Sx, Sy);
    __syncthreads();

    // First 64 threads: merge NCHUNK partials per b and write out.
    if (tid < NB) {
        const int b = tid;
        const float* pM = (const float*)pM2;  // [NCHUNK][NB]
        const float* pS = (const float*)pS2;
        float Mw = pM[b];
#pragma unroll
        for (int c = 1; c < NCHUNK; c++) Mw = fminf(Mw, pM[c * NB + b]);
        float S = 0.0f;
#pragma unroll
        for (int c = 0; c < NCHUNK; c++)
            S = fmaf(pS[c * NB + b], ex2_approx(Mw - pM[c * NB + b]), S);
        out[b * NG + g] = (lg2_approx(S) - Mw) * GLN2;
    }
}

extern "C" void kernel_launch(void* const* d_in, const int* in_sizes, int n_in,
                              void* d_out, int out_size) {
    // Identify inputs by element count:
    //   x:  64*2048   = 131072 float32
    //   I:  2048*32*8 = 524288 int32
    const float* x = nullptr;
    const int* I = nullptr;
    for (int i = 0; i < n_in; i++) {
        if (in_sizes[i] == NB * NG)           x = (const float*)d_in[i];
        else if (in_sizes[i] == NG * NS * NL) I = (const int*)d_in[i];
    }

    float* out = (float*)d_out;  // [64, 2048] fp32

    dim3 tgrid(NG / 32, NB / 32);
    dim3 tblock(32, 8);
    transpose_kernel<<<tgrid, tblock>>>(x);

    // PDL: clause_kernel launches early; gates on transpose completion
    // (trigger placed after the g_w stores) before touching g_w.
    cudaLaunchConfig_t cfg = {};
    cfg.gridDim = dim3(NG);
    cfg.blockDim = dim3(NTHR);
    cfg.dynamicSmemBytes = 0;
    cfg.stream = 0;
    cudaLaunchAttribute attr[1];
    attr[0].id = cudaLaunchAttributeProgrammaticStreamSerialization;
    attr[0].val.programmaticStreamSerializationAllowed = 1;
    cfg.attrs = attr;
    cfg.numAttrs = 1;
    cudaLaunchKernelEx(&cfg, clause_kernel, I, (float*)d_out);
}